// round 1
// baseline (speedup 1.0000x reference)
#include <cuda_runtime.h>
#include <mma.h>
#include <math.h>

using namespace nvcuda;

#define D_   768
#define H_   12
#define HD_  64
#define WSZ  128
#define B_   4
#define L_   8190
#define LP_  8192
#define NTOK (B_*LP_)   /* 32768 */

// Scratch (static device arrays; no runtime allocation)
__device__ float g_q[(size_t)NTOK * D_];
__device__ float g_k[(size_t)NTOK * D_];
__device__ float g_v[(size_t)NTOK * D_];
__device__ float g_o[(size_t)NTOK * D_];
__device__ float g_y[(size_t)NTOK * D_];

template <class F>
__device__ __forceinline__ void cvt_tf32(F& f) {
#pragma unroll
    for (int i = 0; i < f.num_elements; i++) f.x[i] = wmma::__float_to_tf32(f.x[i]);
}

// ---------------------------------------------------------------------------
// Kernel 1: QKV projection.  X[32768,768] (zero-padded rows) @ W[768,768] + b
// Tile: 128(M) x 64(N), K-chunk 32.  8 warps, each 32x32.
// grid = (256, 12, 3); z selects q/k/v.
// ---------------------------------------------------------------------------
__global__ __launch_bounds__(256) void qkv_kernel(
    const float* __restrict__ X,
    const float* __restrict__ Wq, const float* __restrict__ bq,
    const float* __restrict__ Wk, const float* __restrict__ bk,
    const float* __restrict__ Wv, const float* __restrict__ bv)
{
    __shared__ float smem[8704];          // A[128][36] + B[32][68]; reused as staging [128][68]
    float* At = smem;                     // 128*36 = 4608
    float* Bt = smem + 4608;              // 32*68  = 2176

    const float* Wm   = (blockIdx.z == 0) ? Wq : (blockIdx.z == 1) ? Wk : Wv;
    const float* bias = (blockIdx.z == 0) ? bq : (blockIdx.z == 1) ? bk : bv;
    float*       Out  = (blockIdx.z == 0) ? g_q : (blockIdx.z == 1) ? g_k : g_v;

    const int m0 = blockIdx.x * 128;
    const int n0 = blockIdx.y * 64;
    const int tid = threadIdx.x;
    const int wid = tid >> 5;
    const int wm = wid >> 1;   // 0..3
    const int wn = wid & 1;    // 0..1

    wmma::fragment<wmma::accumulator, 16, 16, 8, float> acc[2][2];
#pragma unroll
    for (int i = 0; i < 2; i++)
#pragma unroll
        for (int j = 0; j < 2; j++) wmma::fill_fragment(acc[i][j], 0.0f);

    for (int k0 = 0; k0 < D_; k0 += 32) {
        // load A tile (zero-fill padded tokens)
#pragma unroll
        for (int it = 0; it < 4; it++) {
            int idx = tid + it * 256;             // 0..1023
            int r = idx >> 3;
            int c4 = (idx & 7) * 4;
            int tok = m0 + r;
            int b = tok >> 13;
            int l = tok & (LP_ - 1);
            float4 vv = make_float4(0.f, 0.f, 0.f, 0.f);
            if (l < L_)
                vv = *(const float4*)(X + (size_t)(b * L_ + l) * D_ + k0 + c4);
            *(float4*)(At + r * 36 + c4) = vv;
        }
        // load B tile
#pragma unroll
        for (int it = 0; it < 2; it++) {
            int idx = tid + it * 256;             // 0..511
            int r = idx >> 4;
            int c4 = (idx & 15) * 4;
            *(float4*)(Bt + r * 68 + c4) =
                *(const float4*)(Wm + (size_t)(k0 + r) * D_ + n0 + c4);
        }
        __syncthreads();

#pragma unroll
        for (int kk = 0; kk < 4; kk++) {
            wmma::fragment<wmma::matrix_a, 16, 16, 8, wmma::precision::tf32, wmma::row_major> a0, a1;
            wmma::fragment<wmma::matrix_b, 16, 16, 8, wmma::precision::tf32, wmma::row_major> b0, b1;
            wmma::load_matrix_sync(a0, At + (wm * 32) * 36 + kk * 8, 36);
            wmma::load_matrix_sync(a1, At + (wm * 32 + 16) * 36 + kk * 8, 36);
            wmma::load_matrix_sync(b0, Bt + (kk * 8) * 68 + wn * 32, 68);
            wmma::load_matrix_sync(b1, Bt + (kk * 8) * 68 + wn * 32 + 16, 68);
            cvt_tf32(a0); cvt_tf32(a1); cvt_tf32(b0); cvt_tf32(b1);
            wmma::mma_sync(acc[0][0], a0, b0, acc[0][0]);
            wmma::mma_sync(acc[0][1], a0, b1, acc[0][1]);
            wmma::mma_sync(acc[1][0], a1, b0, acc[1][0]);
            wmma::mma_sync(acc[1][1], a1, b1, acc[1][1]);
        }
        __syncthreads();
    }

    // epilogue via smem staging
    float* St = smem;  // [128][68]
#pragma unroll
    for (int i = 0; i < 2; i++)
#pragma unroll
        for (int j = 0; j < 2; j++)
            wmma::store_matrix_sync(St + (wm * 32 + i * 16) * 68 + wn * 32 + j * 16,
                                    acc[i][j], 68, wmma::mem_row_major);
    __syncthreads();
#pragma unroll
    for (int it = 0; it < 32; it++) {
        int idx = tid + it * 256;               // 0..8191
        int r = idx >> 6;
        int c = idx & 63;
        float v = St[r * 68 + c] + bias[n0 + c];
        Out[(size_t)(m0 + r) * D_ + n0 + c] = v;
    }
}

// ---------------------------------------------------------------------------
// Kernel 2: per-(window, head) attention.  q,k,v [128,64] -> o [128,64]
// grid = (12 heads, 256 windows); 256 threads.
// ---------------------------------------------------------------------------
#define ATTN_SMEM ((3 * 128 * 72 + 128 * 132) * 4)

__global__ __launch_bounds__(256) void attn_kernel()
{
    extern __shared__ float sm[];
    float* Q = sm;                  // [128][72]
    float* K = Q + 128 * 72;
    float* V = K + 128 * 72;
    float* S = V + 128 * 72;        // [128][132]

    const int h = blockIdx.x;
    const int gw = blockIdx.y;        // gw = b*64 + w  ->  token base = gw*128
    const int tok0 = gw * 128;
    const int tid = threadIdx.x;
    const int wid = tid >> 5;
    const int wm = wid >> 1;          // 0..3
    const int wn = wid & 1;           // 0..1

    // load q,k,v tiles
#pragma unroll
    for (int it = 0; it < 8; it++) {
        int idx = tid + it * 256;     // 0..2047
        int r = idx >> 4;
        int c4 = (idx & 15) * 4;
        size_t g = (size_t)(tok0 + r) * D_ + h * HD_ + c4;
        *(float4*)(Q + r * 72 + c4) = *(const float4*)(g_q + g);
        *(float4*)(K + r * 72 + c4) = *(const float4*)(g_k + g);
        *(float4*)(V + r * 72 + c4) = *(const float4*)(g_v + g);
    }
    __syncthreads();

    // S = Q @ K^T  : each warp 32x64
    {
        wmma::fragment<wmma::accumulator, 16, 16, 8, float> acc[2][4];
#pragma unroll
        for (int i = 0; i < 2; i++)
#pragma unroll
            for (int j = 0; j < 4; j++) wmma::fill_fragment(acc[i][j], 0.0f);

#pragma unroll
        for (int kk = 0; kk < 8; kk++) {
            wmma::fragment<wmma::matrix_a, 16, 16, 8, wmma::precision::tf32, wmma::row_major> a0, a1;
            wmma::load_matrix_sync(a0, Q + (wm * 32) * 72 + kk * 8, 72);
            wmma::load_matrix_sync(a1, Q + (wm * 32 + 16) * 72 + kk * 8, 72);
            cvt_tf32(a0); cvt_tf32(a1);
#pragma unroll
            for (int j = 0; j < 4; j++) {
                wmma::fragment<wmma::matrix_b, 16, 16, 8, wmma::precision::tf32, wmma::col_major> bf;
                wmma::load_matrix_sync(bf, K + (wn * 64 + j * 16) * 72 + kk * 8, 72);
                cvt_tf32(bf);
                wmma::mma_sync(acc[0][j], a0, bf, acc[0][j]);
                wmma::mma_sync(acc[1][j], a1, bf, acc[1][j]);
            }
        }
#pragma unroll
        for (int i = 0; i < 2; i++)
#pragma unroll
            for (int j = 0; j < 4; j++)
                wmma::store_matrix_sync(S + (wm * 32 + i * 16) * 132 + wn * 64 + j * 16,
                                        acc[i][j], 132, wmma::mem_row_major);
    }
    __syncthreads();

    // softmax (rows), scale = 1/sqrt(64)
    if (tid < 128) {
        float* row = S + tid * 132;
        const float scale = 0.125f;
        float mx = -3.4e38f;
#pragma unroll 4
        for (int j = 0; j < 128; j++) mx = fmaxf(mx, row[j] * scale);
        float sum = 0.0f;
#pragma unroll 4
        for (int j = 0; j < 128; j++) {
            float e = __expf(row[j] * scale - mx);
            row[j] = e;
            sum += e;
        }
        float inv = 1.0f / sum;
#pragma unroll 4
        for (int j = 0; j < 128; j++) row[j] *= inv;
    }
    __syncthreads();

    // O = P @ V : each warp 32x32
    {
        wmma::fragment<wmma::accumulator, 16, 16, 8, float> acc[2][2];
#pragma unroll
        for (int i = 0; i < 2; i++)
#pragma unroll
            for (int j = 0; j < 2; j++) wmma::fill_fragment(acc[i][j], 0.0f);

#pragma unroll
        for (int kk = 0; kk < 16; kk++) {
            wmma::fragment<wmma::matrix_a, 16, 16, 8, wmma::precision::tf32, wmma::row_major> a0, a1;
            wmma::fragment<wmma::matrix_b, 16, 16, 8, wmma::precision::tf32, wmma::row_major> b0, b1;
            wmma::load_matrix_sync(a0, S + (wm * 32) * 132 + kk * 8, 132);
            wmma::load_matrix_sync(a1, S + (wm * 32 + 16) * 132 + kk * 8, 132);
            wmma::load_matrix_sync(b0, V + (kk * 8) * 72 + wn * 32, 72);
            wmma::load_matrix_sync(b1, V + (kk * 8) * 72 + wn * 32 + 16, 72);
            cvt_tf32(a0); cvt_tf32(a1); cvt_tf32(b0); cvt_tf32(b1);
            wmma::mma_sync(acc[0][0], a0, b0, acc[0][0]);
            wmma::mma_sync(acc[0][1], a0, b1, acc[0][1]);
            wmma::mma_sync(acc[1][0], a1, b0, acc[1][0]);
            wmma::mma_sync(acc[1][1], a1, b1, acc[1][1]);
        }
        // direct global store
#pragma unroll
        for (int i = 0; i < 2; i++)
#pragma unroll
            for (int j = 0; j < 2; j++)
                wmma::store_matrix_sync(
                    g_o + (size_t)(tok0 + wm * 32 + i * 16) * D_ + h * HD_ + wn * 32 + j * 16,
                    acc[i][j], D_, wmma::mem_row_major);
    }
}

// ---------------------------------------------------------------------------
// Kernel 3: y = O @ Wo + bo + residual(x).  grid = (256, 12)
// ---------------------------------------------------------------------------
__global__ __launch_bounds__(256) void oproj_kernel(
    const float* __restrict__ X,
    const float* __restrict__ Wo, const float* __restrict__ bo)
{
    __shared__ float smem[8704];
    float* At = smem;
    float* Bt = smem + 4608;

    const int m0 = blockIdx.x * 128;
    const int n0 = blockIdx.y * 64;
    const int tid = threadIdx.x;
    const int wid = tid >> 5;
    const int wm = wid >> 1;
    const int wn = wid & 1;

    wmma::fragment<wmma::accumulator, 16, 16, 8, float> acc[2][2];
#pragma unroll
    for (int i = 0; i < 2; i++)
#pragma unroll
        for (int j = 0; j < 2; j++) wmma::fill_fragment(acc[i][j], 0.0f);

    for (int k0 = 0; k0 < D_; k0 += 32) {
#pragma unroll
        for (int it = 0; it < 4; it++) {
            int idx = tid + it * 256;
            int r = idx >> 3;
            int c4 = (idx & 7) * 4;
            *(float4*)(At + r * 36 + c4) =
                *(const float4*)(g_o + (size_t)(m0 + r) * D_ + k0 + c4);
        }
#pragma unroll
        for (int it = 0; it < 2; it++) {
            int idx = tid + it * 256;
            int r = idx >> 4;
            int c4 = (idx & 15) * 4;
            *(float4*)(Bt + r * 68 + c4) =
                *(const float4*)(Wo + (size_t)(k0 + r) * D_ + n0 + c4);
        }
        __syncthreads();
#pragma unroll
        for (int kk = 0; kk < 4; kk++) {
            wmma::fragment<wmma::matrix_a, 16, 16, 8, wmma::precision::tf32, wmma::row_major> a0, a1;
            wmma::fragment<wmma::matrix_b, 16, 16, 8, wmma::precision::tf32, wmma::row_major> b0, b1;
            wmma::load_matrix_sync(a0, At + (wm * 32) * 36 + kk * 8, 36);
            wmma::load_matrix_sync(a1, At + (wm * 32 + 16) * 36 + kk * 8, 36);
            wmma::load_matrix_sync(b0, Bt + (kk * 8) * 68 + wn * 32, 68);
            wmma::load_matrix_sync(b1, Bt + (kk * 8) * 68 + wn * 32 + 16, 68);
            cvt_tf32(a0); cvt_tf32(a1); cvt_tf32(b0); cvt_tf32(b1);
            wmma::mma_sync(acc[0][0], a0, b0, acc[0][0]);
            wmma::mma_sync(acc[0][1], a0, b1, acc[0][1]);
            wmma::mma_sync(acc[1][0], a1, b0, acc[1][0]);
            wmma::mma_sync(acc[1][1], a1, b1, acc[1][1]);
        }
        __syncthreads();
    }

    float* St = smem;
#pragma unroll
    for (int i = 0; i < 2; i++)
#pragma unroll
        for (int j = 0; j < 2; j++)
            wmma::store_matrix_sync(St + (wm * 32 + i * 16) * 68 + wn * 32 + j * 16,
                                    acc[i][j], 68, wmma::mem_row_major);
    __syncthreads();
#pragma unroll
    for (int it = 0; it < 32; it++) {
        int idx = tid + it * 256;
        int r = idx >> 6;
        int c = idx & 63;
        int tok = m0 + r;
        int b = tok >> 13;
        int l = tok & (LP_ - 1);
        float res = (l < L_) ? X[(size_t)(b * L_ + l) * D_ + n0 + c] : 0.0f;
        g_y[(size_t)tok * D_ + n0 + c] = St[r * 68 + c] + bo[n0 + c] + res;
    }
}

// ---------------------------------------------------------------------------
// Kernel 4: LayerNorm over D.  grid = 32760 (valid tokens), 256 threads.
// ---------------------------------------------------------------------------
__global__ __launch_bounds__(256) void ln_kernel(
    const float* __restrict__ gam, const float* __restrict__ bet,
    float* __restrict__ out)
{
    const int t = blockIdx.x;              // 0..32759 (b*8190 + l)
    const int b = t / L_;
    const int l = t - b * L_;
    const float* y = g_y + (size_t)(b * LP_ + l) * D_;
    const int tid = threadIdx.x;

    float v0 = y[tid], v1 = y[tid + 256], v2 = y[tid + 512];
    float s = v0 + v1 + v2;
    float ss = v0 * v0 + v1 * v1 + v2 * v2;

    __shared__ float red_s[8], red_q[8];
#pragma unroll
    for (int off = 16; off > 0; off >>= 1) {
        s += __shfl_down_sync(0xffffffffu, s, off);
        ss += __shfl_down_sync(0xffffffffu, ss, off);
    }
    if ((tid & 31) == 0) { red_s[tid >> 5] = s; red_q[tid >> 5] = ss; }
    __syncthreads();
    if (tid < 32) {
        float a = (tid < 8) ? red_s[tid] : 0.0f;
        float q = (tid < 8) ? red_q[tid] : 0.0f;
#pragma unroll
        for (int off = 4; off > 0; off >>= 1) {
            a += __shfl_down_sync(0xffffffffu, a, off);
            q += __shfl_down_sync(0xffffffffu, q, off);
        }
        if (tid == 0) { red_s[0] = a; red_q[0] = q; }
    }
    __syncthreads();

    float mu = red_s[0] * (1.0f / D_);
    float var = red_q[0] * (1.0f / D_) - mu * mu;
    float inv = rsqrtf(var + 1e-5f);

    float* o = out + (size_t)t * D_;
    o[tid]       = (v0 - mu) * inv * gam[tid]       + bet[tid];
    o[tid + 256] = (v1 - mu) * inv * gam[tid + 256] + bet[tid + 256];
    o[tid + 512] = (v2 - mu) * inv * gam[tid + 512] + bet[tid + 512];
}

// ---------------------------------------------------------------------------
extern "C" void kernel_launch(void* const* d_in, const int* in_sizes, int n_in,
                              void* d_out, int out_size)
{
    const float* x    = (const float*)d_in[0];
    const float* Wq   = (const float*)d_in[1];
    const float* bq   = (const float*)d_in[2];
    const float* Wk   = (const float*)d_in[3];
    const float* bk   = (const float*)d_in[4];
    const float* Wv   = (const float*)d_in[5];
    const float* bv   = (const float*)d_in[6];
    const float* Wo   = (const float*)d_in[7];
    const float* bo   = (const float*)d_in[8];
    const float* ln_g = (const float*)d_in[9];
    const float* ln_b = (const float*)d_in[10];
    float* out = (float*)d_out;

    cudaFuncSetAttribute(attn_kernel, cudaFuncAttributeMaxDynamicSharedMemorySize, ATTN_SMEM);

    qkv_kernel<<<dim3(NTOK / 128, D_ / 64, 3), 256>>>(x, Wq, bq, Wk, bk, Wv, bv);
    attn_kernel<<<dim3(H_, NTOK / WSZ), 256, ATTN_SMEM>>>();
    oproj_kernel<<<dim3(NTOK / 128, D_ / 64), 256>>>(x, Wo, bo);
    ln_kernel<<<B_ * L_, 256>>>(ln_g, ln_b, out);
}

// round 2
// speedup vs baseline: 1.3183x; 1.3183x over previous
#include <cuda_runtime.h>
#include <mma.h>
#include <math.h>

using namespace nvcuda;

#define D_   768
#define H_   12
#define HD_  64
#define WSZ  128
#define B_   4
#define L_   8190
#define LP_  8192
#define NTOK (B_*LP_)   /* 32768 */

// Scratch (static device arrays; no runtime allocation)
__device__ float g_x[(size_t)NTOK * D_];     // rounded + zero-padded input
__device__ float g_w[4 * 589824];            // rounded Wq,Wk,Wv,Wo
__device__ float g_q[(size_t)NTOK * D_];
__device__ float g_k[(size_t)NTOK * D_];
__device__ float g_v[(size_t)NTOK * D_];
__device__ float g_o[(size_t)NTOK * D_];
__device__ float g_y[(size_t)NTOK * D_];

__device__ __forceinline__ void cpa16(float* s, const float* g) {
    unsigned sa = (unsigned)__cvta_generic_to_shared(s);
    asm volatile("cp.async.cg.shared.global [%0], [%1], 16;" :: "r"(sa), "l"(g));
}

// ---------------------------------------------------------------------------
// Prep: round x to tf32 into dense zero-padded g_x
// ---------------------------------------------------------------------------
__global__ __launch_bounds__(256) void prep_x(const float* __restrict__ X)
{
    size_t fidx = (size_t)blockIdx.x * 256 + threadIdx.x;   // over 6291456 float4s
    int tok = (int)(fidx / 192);
    int c4  = (int)(fidx - (size_t)tok * 192) * 4;
    int b = tok >> 13;
    int l = tok & (LP_ - 1);
    float4 v = make_float4(0.f, 0.f, 0.f, 0.f);
    if (l < L_) v = *(const float4*)(X + (size_t)(b * L_ + l) * D_ + c4);
    v.x = wmma::__float_to_tf32(v.x);
    v.y = wmma::__float_to_tf32(v.y);
    v.z = wmma::__float_to_tf32(v.z);
    v.w = wmma::__float_to_tf32(v.w);
    *(float4*)(g_x + fidx * 4) = v;
}

__global__ __launch_bounds__(256) void prep_w(
    const float* __restrict__ Wq, const float* __restrict__ Wk,
    const float* __restrict__ Wv, const float* __restrict__ Wo)
{
    int idx = blockIdx.x * 256 + threadIdx.x;               // over 589824 float4s
    int m = idx / 147456;
    int off4 = (idx - m * 147456) * 4;
    const float* src = (m == 0) ? Wq : (m == 1) ? Wk : (m == 2) ? Wv : Wo;
    float4 v = *(const float4*)(src + off4);
    v.x = wmma::__float_to_tf32(v.x);
    v.y = wmma::__float_to_tf32(v.y);
    v.z = wmma::__float_to_tf32(v.z);
    v.w = wmma::__float_to_tf32(v.w);
    *(float4*)(g_w + (size_t)m * 589824 + off4) = v;
}

// ---------------------------------------------------------------------------
// Pipelined GEMM: C[128,128] tile, K-chunk 16, double-buffered cp.async.
// MODE 0: qkv (A=g_x, W by blockIdx.z, out g_q/g_k/g_v, +bias, round)
// MODE 1: oproj (A=g_o, W=Wo, out g_y, +bias +residual, no round)
// ---------------------------------------------------------------------------
#define AS_STRIDE 20
#define BS_STRIDE 132
#define AS_BUF (128 * AS_STRIDE)     /* 2560 */
#define BS_BUF (16 * BS_STRIDE)      /* 2112 */
#define GEMM_SMEM (128 * 132 * 4)    /* 67584 B staging; pipeline fits inside */

typedef wmma::fragment<wmma::matrix_a, 16, 16, 8, wmma::precision::tf32, wmma::row_major> FragA;
typedef wmma::fragment<wmma::matrix_b, 16, 16, 8, wmma::precision::tf32, wmma::row_major> FragB;
typedef wmma::fragment<wmma::accumulator, 16, 16, 8, float> FragC;

__device__ __forceinline__ void ld_tiles(const float* Ap, const float* Wp,
                                         float* As, float* Bs,
                                         int tid, int m0, int n0, int k0)
{
#pragma unroll
    for (int it = 0; it < 2; it++) {
        int idx = tid + it * 256;
        int r = idx >> 2, c4 = (idx & 3) << 2;
        cpa16(As + r * AS_STRIDE + c4, Ap + (size_t)(m0 + r) * D_ + k0 + c4);
    }
#pragma unroll
    for (int it = 0; it < 2; it++) {
        int idx = tid + it * 256;
        int r = idx >> 5, c4 = (idx & 31) << 2;
        cpa16(Bs + r * BS_STRIDE + c4, Wp + (size_t)(k0 + r) * D_ + n0 + c4);
    }
}

template <int MODE>
__global__ __launch_bounds__(256) void gemm_kernel(
    const float* __restrict__ b0, const float* __restrict__ b1,
    const float* __restrict__ b2, const float* __restrict__ X)
{
    extern __shared__ float sm[];
    float* As = sm;                 // [2][AS_BUF]
    float* Bs = sm + 2 * AS_BUF;    // [2][BS_BUF]

    const int m0 = blockIdx.x * 128;
    const int n0 = blockIdx.y * 128;
    const int z  = (MODE == 0) ? blockIdx.z : 3;
    const float* Ap = (MODE == 0) ? g_x : g_o;
    const float* Wp = g_w + (size_t)z * 589824;

    const int tid = threadIdx.x;
    const int wid = tid >> 5;
    const int wm = wid >> 2;   // 0..1  (64 rows)
    const int wn = wid & 3;    // 0..3  (32 cols)

    FragC acc[4][2];
#pragma unroll
    for (int i = 0; i < 4; i++)
#pragma unroll
        for (int j = 0; j < 2; j++) wmma::fill_fragment(acc[i][j], 0.0f);

    ld_tiles(Ap, Wp, As, Bs, tid, m0, n0, 0);
    asm volatile("cp.async.commit_group;");

    for (int it = 0; it < 48; it++) {
        if (it < 47) {
            int nb = (it + 1) & 1;
            ld_tiles(Ap, Wp, As + nb * AS_BUF, Bs + nb * BS_BUF, tid, m0, n0, (it + 1) * 16);
            asm volatile("cp.async.commit_group;");
            asm volatile("cp.async.wait_group 1;");
        } else {
            asm volatile("cp.async.wait_group 0;");
        }
        __syncthreads();

        const float* Ab = As + (it & 1) * AS_BUF;
        const float* Bb = Bs + (it & 1) * BS_BUF;
#pragma unroll
        for (int ks = 0; ks < 2; ks++) {
            FragA a[4];
            FragB b[2];
#pragma unroll
            for (int i = 0; i < 4; i++)
                wmma::load_matrix_sync(a[i], Ab + (wm * 64 + i * 16) * AS_STRIDE + ks * 8, AS_STRIDE);
#pragma unroll
            for (int j = 0; j < 2; j++)
                wmma::load_matrix_sync(b[j], Bb + (ks * 8) * BS_STRIDE + wn * 32 + j * 16, BS_STRIDE);
#pragma unroll
            for (int i = 0; i < 4; i++)
#pragma unroll
                for (int j = 0; j < 2; j++)
                    wmma::mma_sync(acc[i][j], a[i], b[j], acc[i][j]);
        }
        __syncthreads();
    }

    // epilogue via smem staging
    float* St = sm;  // [128][132]
#pragma unroll
    for (int i = 0; i < 4; i++)
#pragma unroll
        for (int j = 0; j < 2; j++)
            wmma::store_matrix_sync(St + (wm * 64 + i * 16) * BS_STRIDE + wn * 32 + j * 16,
                                    acc[i][j], BS_STRIDE, wmma::mem_row_major);
    __syncthreads();

    if (MODE == 0) {
        const float* bb = (z == 0) ? b0 : (z == 1) ? b1 : b2;
        float* Out = (z == 0) ? g_q : (z == 1) ? g_k : g_v;
#pragma unroll
        for (int it = 0; it < 16; it++) {
            int idx = tid + it * 256;
            int r = idx >> 5, c4 = (idx & 31) << 2;
            float4 v = *(const float4*)(St + r * BS_STRIDE + c4);
            const float4 bv = *(const float4*)(bb + n0 + c4);
            v.x = wmma::__float_to_tf32(v.x + bv.x);
            v.y = wmma::__float_to_tf32(v.y + bv.y);
            v.z = wmma::__float_to_tf32(v.z + bv.z);
            v.w = wmma::__float_to_tf32(v.w + bv.w);
            *(float4*)(Out + (size_t)(m0 + r) * D_ + n0 + c4) = v;
        }
    } else {
#pragma unroll
        for (int it = 0; it < 16; it++) {
            int idx = tid + it * 256;
            int r = idx >> 5, c4 = (idx & 31) << 2;
            float4 v = *(const float4*)(St + r * BS_STRIDE + c4);
            const float4 bv = *(const float4*)(b0 + n0 + c4);
            int tok = m0 + r;
            int b = tok >> 13;
            int l = tok & (LP_ - 1);
            float4 res = make_float4(0.f, 0.f, 0.f, 0.f);
            if (l < L_) res = *(const float4*)(X + (size_t)(b * L_ + l) * D_ + n0 + c4);
            v.x += bv.x + res.x;
            v.y += bv.y + res.y;
            v.z += bv.z + res.z;
            v.w += bv.w + res.w;
            *(float4*)(g_y + (size_t)tok * D_ + n0 + c4) = v;
        }
    }
}

// ---------------------------------------------------------------------------
// Attention per (head, window). Inputs pre-rounded tf32 -> no in-loop cvt.
// ---------------------------------------------------------------------------
#define QKV_STRIDE 68
#define S_STRIDE   132
#define ATTN_SMEM ((3 * 128 * QKV_STRIDE + 128 * S_STRIDE) * 4)

__global__ __launch_bounds__(256) void attn_kernel()
{
    extern __shared__ float sm[];
    float* Q = sm;                        // [128][68]
    float* K = Q + 128 * QKV_STRIDE;
    float* V = K + 128 * QKV_STRIDE;
    float* S = V + 128 * QKV_STRIDE;      // [128][132]

    const int h = blockIdx.x;
    const int tok0 = blockIdx.y * 128;
    const int tid = threadIdx.x;
    const int wid = tid >> 5;
    const int wm = wid >> 1;              // 0..3 (32-row)
    const int wn = wid & 1;               // 0..1

#pragma unroll
    for (int it = 0; it < 8; it++) {
        int idx = tid + it * 256;         // 0..2047
        int r = idx >> 4;
        int c4 = (idx & 15) * 4;
        size_t g = (size_t)(tok0 + r) * D_ + h * HD_ + c4;
        *(float4*)(Q + r * QKV_STRIDE + c4) = *(const float4*)(g_q + g);
        *(float4*)(K + r * QKV_STRIDE + c4) = *(const float4*)(g_k + g);
        *(float4*)(V + r * QKV_STRIDE + c4) = *(const float4*)(g_v + g);
    }
    __syncthreads();

    // S = Q @ K^T  (each warp 32x64)
    {
        FragC acc[2][4];
#pragma unroll
        for (int i = 0; i < 2; i++)
#pragma unroll
            for (int j = 0; j < 4; j++) wmma::fill_fragment(acc[i][j], 0.0f);

#pragma unroll
        for (int kk = 0; kk < 8; kk++) {
            FragA a0, a1;
            wmma::load_matrix_sync(a0, Q + (wm * 32) * QKV_STRIDE + kk * 8, QKV_STRIDE);
            wmma::load_matrix_sync(a1, Q + (wm * 32 + 16) * QKV_STRIDE + kk * 8, QKV_STRIDE);
#pragma unroll
            for (int j = 0; j < 4; j++) {
                wmma::fragment<wmma::matrix_b, 16, 16, 8, wmma::precision::tf32, wmma::col_major> bf;
                wmma::load_matrix_sync(bf, K + (wn * 64 + j * 16) * QKV_STRIDE + kk * 8, QKV_STRIDE);
                wmma::mma_sync(acc[0][j], a0, bf, acc[0][j]);
                wmma::mma_sync(acc[1][j], a1, bf, acc[1][j]);
            }
        }
#pragma unroll
        for (int i = 0; i < 2; i++)
#pragma unroll
            for (int j = 0; j < 4; j++)
                wmma::store_matrix_sync(S + (wm * 32 + i * 16) * S_STRIDE + wn * 64 + j * 16,
                                        acc[i][j], S_STRIDE, wmma::mem_row_major);
    }
    __syncthreads();

    // softmax per row (threads 0..127), float4-vectorized, output rounded to tf32
    if (tid < 128) {
        float4* row = (float4*)(S + tid * S_STRIDE);
        const float scale = 0.125f;
        float mx = -3.4e38f;
#pragma unroll
        for (int j = 0; j < 32; j++) {
            float4 v = row[j];
            mx = fmaxf(mx, fmaxf(fmaxf(v.x, v.y), fmaxf(v.z, v.w)));
        }
        mx *= scale;
        float sum = 0.0f;
#pragma unroll
        for (int j = 0; j < 32; j++) {
            float4 v = row[j];
            v.x = __expf(v.x * scale - mx);
            v.y = __expf(v.y * scale - mx);
            v.z = __expf(v.z * scale - mx);
            v.w = __expf(v.w * scale - mx);
            sum += v.x + v.y + v.z + v.w;
            row[j] = v;
        }
        float inv = 1.0f / sum;
#pragma unroll
        for (int j = 0; j < 32; j++) {
            float4 v = row[j];
            v.x = wmma::__float_to_tf32(v.x * inv);
            v.y = wmma::__float_to_tf32(v.y * inv);
            v.z = wmma::__float_to_tf32(v.z * inv);
            v.w = wmma::__float_to_tf32(v.w * inv);
            row[j] = v;
        }
    }
    __syncthreads();

    // O = P @ V (each warp 32x32), round accumulator, store direct to g_o
    {
        FragC acc[2][2];
#pragma unroll
        for (int i = 0; i < 2; i++)
#pragma unroll
            for (int j = 0; j < 2; j++) wmma::fill_fragment(acc[i][j], 0.0f);

#pragma unroll
        for (int kk = 0; kk < 16; kk++) {
            FragA a0, a1;
            FragB bf0, bf1;
            wmma::load_matrix_sync(a0, S + (wm * 32) * S_STRIDE + kk * 8, S_STRIDE);
            wmma::load_matrix_sync(a1, S + (wm * 32 + 16) * S_STRIDE + kk * 8, S_STRIDE);
            wmma::load_matrix_sync(bf0, V + (kk * 8) * QKV_STRIDE + wn * 32, QKV_STRIDE);
            wmma::load_matrix_sync(bf1, V + (kk * 8) * QKV_STRIDE + wn * 32 + 16, QKV_STRIDE);
            wmma::mma_sync(acc[0][0], a0, bf0, acc[0][0]);
            wmma::mma_sync(acc[0][1], a0, bf1, acc[0][1]);
            wmma::mma_sync(acc[1][0], a1, bf0, acc[1][0]);
            wmma::mma_sync(acc[1][1], a1, bf1, acc[1][1]);
        }
#pragma unroll
        for (int i = 0; i < 2; i++)
#pragma unroll
            for (int j = 0; j < 2; j++) {
#pragma unroll
                for (int e = 0; e < acc[i][j].num_elements; e++)
                    acc[i][j].x[e] = wmma::__float_to_tf32(acc[i][j].x[e]);
                wmma::store_matrix_sync(
                    g_o + (size_t)(tok0 + wm * 32 + i * 16) * D_ + h * HD_ + wn * 32 + j * 16,
                    acc[i][j], D_, wmma::mem_row_major);
            }
    }
}

// ---------------------------------------------------------------------------
// LayerNorm over D. grid = 32760 valid tokens.
// ---------------------------------------------------------------------------
__global__ __launch_bounds__(256) void ln_kernel(
    const float* __restrict__ gam, const float* __restrict__ bet,
    float* __restrict__ out)
{
    const int t = blockIdx.x;
    const int b = t / L_;
    const int l = t - b * L_;
    const float* y = g_y + (size_t)(b * LP_ + l) * D_;
    const int tid = threadIdx.x;

    float v0 = y[tid], v1 = y[tid + 256], v2 = y[tid + 512];
    float s = v0 + v1 + v2;
    float ss = v0 * v0 + v1 * v1 + v2 * v2;

    __shared__ float red_s[8], red_q[8];
#pragma unroll
    for (int off = 16; off > 0; off >>= 1) {
        s += __shfl_down_sync(0xffffffffu, s, off);
        ss += __shfl_down_sync(0xffffffffu, ss, off);
    }
    if ((tid & 31) == 0) { red_s[tid >> 5] = s; red_q[tid >> 5] = ss; }
    __syncthreads();
    if (tid < 32) {
        float a = (tid < 8) ? red_s[tid] : 0.0f;
        float q = (tid < 8) ? red_q[tid] : 0.0f;
#pragma unroll
        for (int off = 4; off > 0; off >>= 1) {
            a += __shfl_down_sync(0xffffffffu, a, off);
            q += __shfl_down_sync(0xffffffffu, q, off);
        }
        if (tid == 0) { red_s[0] = a; red_q[0] = q; }
    }
    __syncthreads();

    float mu = red_s[0] * (1.0f / D_);
    float var = red_q[0] * (1.0f / D_) - mu * mu;
    float inv = rsqrtf(var + 1e-5f);

    float* o = out + (size_t)t * D_;
    o[tid]       = (v0 - mu) * inv * gam[tid]       + bet[tid];
    o[tid + 256] = (v1 - mu) * inv * gam[tid + 256] + bet[tid + 256];
    o[tid + 512] = (v2 - mu) * inv * gam[tid + 512] + bet[tid + 512];
}

// ---------------------------------------------------------------------------
extern "C" void kernel_launch(void* const* d_in, const int* in_sizes, int n_in,
                              void* d_out, int out_size)
{
    const float* x    = (const float*)d_in[0];
    const float* Wq   = (const float*)d_in[1];
    const float* bq   = (const float*)d_in[2];
    const float* Wk   = (const float*)d_in[3];
    const float* bk   = (const float*)d_in[4];
    const float* Wv   = (const float*)d_in[5];
    const float* bv   = (const float*)d_in[6];
    const float* Wo   = (const float*)d_in[7];
    const float* bo   = (const float*)d_in[8];
    const float* ln_g = (const float*)d_in[9];
    const float* ln_b = (const float*)d_in[10];
    float* out = (float*)d_out;

    cudaFuncSetAttribute(gemm_kernel<0>, cudaFuncAttributeMaxDynamicSharedMemorySize, GEMM_SMEM);
    cudaFuncSetAttribute(gemm_kernel<1>, cudaFuncAttributeMaxDynamicSharedMemorySize, GEMM_SMEM);
    cudaFuncSetAttribute(attn_kernel, cudaFuncAttributeMaxDynamicSharedMemorySize, ATTN_SMEM);

    prep_x<<<24576, 256>>>(x);
    prep_w<<<2304, 256>>>(Wq, Wk, Wv, Wo);
    gemm_kernel<0><<<dim3(NTOK / 128, D_ / 128, 3), 256, GEMM_SMEM>>>(bq, bk, bv, nullptr);
    attn_kernel<<<dim3(H_, NTOK / WSZ), 256, ATTN_SMEM>>>();
    gemm_kernel<1><<<dim3(NTOK / 128, D_ / 128, 1), 256, GEMM_SMEM>>>(bo, nullptr, nullptr, x);
    ln_kernel<<<B_ * L_, 256>>>(ln_g, ln_b, out);
}

// round 4
// speedup vs baseline: 1.3284x; 1.0077x over previous
#include <cuda_runtime.h>
#include <mma.h>
#include <math.h>
#include <stdint.h>

using namespace nvcuda;

#define D_   768
#define H_   12
#define HD_  64
#define WSZ  128
#define B_   4
#define L_   8190
#define LP_  8192
#define NTOK (B_*LP_)   /* 32768 */

// Scratch
__device__ float g_x[(size_t)NTOK * D_];     // rounded + zero-padded input
__device__ float g_wt[4 * 589824];           // rounded, TRANSPOSED weights: [z*768+n][k]
__device__ float g_bias[4 * D_];             // concat bq,bk,bv,bo
__device__ float g_q[(size_t)NTOK * D_];
__device__ float g_k[(size_t)NTOK * D_];
__device__ float g_v[(size_t)NTOK * D_];
__device__ float g_o[(size_t)NTOK * D_];
__device__ float g_y[(size_t)NTOK * D_];

__device__ __forceinline__ void cpa16(uint32_t s, const float* g) {
    asm volatile("cp.async.cg.shared.global [%0], [%1], 16;" :: "r"(s), "l"(g));
}
template<int N> __device__ __forceinline__ void cp_wait() {
    asm volatile("cp.async.wait_group %0;" :: "n"(N));
}
__device__ __forceinline__ void cp_commit() {
    asm volatile("cp.async.commit_group;");
}
__device__ __forceinline__ uint32_t smem_u32(const void* p) {
    uint32_t a;
    asm("{ .reg .u64 t; cvta.to.shared.u64 t, %1; cvt.u32.u64 %0, t; }" : "=r"(a) : "l"(p));
    return a;
}

extern __shared__ __align__(1024) float dynsm[];

// ---------------------------------------------------------------------------
// Prep kernels
// ---------------------------------------------------------------------------
__global__ __launch_bounds__(256) void prep_x(const float* __restrict__ X)
{
    size_t fidx = (size_t)blockIdx.x * 256 + threadIdx.x;   // 6291456 float4s
    int tok = (int)(fidx / 192);
    int c4  = (int)(fidx - (size_t)tok * 192) * 4;
    int b = tok >> 13;
    int l = tok & (LP_ - 1);
    float4 v = make_float4(0.f, 0.f, 0.f, 0.f);
    if (l < L_) v = *(const float4*)(X + (size_t)(b * L_ + l) * D_ + c4);
    v.x = wmma::__float_to_tf32(v.x);
    v.y = wmma::__float_to_tf32(v.y);
    v.z = wmma::__float_to_tf32(v.z);
    v.w = wmma::__float_to_tf32(v.w);
    *(float4*)(g_x + fidx * 4) = v;
}

// transpose + round weights: g_wt[(z*768 + n)*768 + k] = rnd(W_z[k][n])
__global__ __launch_bounds__(256) void prep_wt(
    const float* __restrict__ Wq, const float* __restrict__ Wk,
    const float* __restrict__ Wv, const float* __restrict__ Wo)
{
    __shared__ float t[32][33];
    const int z = blockIdx.z;
    const float* W = (z == 0) ? Wq : (z == 1) ? Wk : (z == 2) ? Wv : Wo;
    const int k0 = blockIdx.x * 32;
    const int n0 = blockIdx.y * 32;
    const int tx = threadIdx.x & 31;
    const int ty = threadIdx.x >> 5;      // 0..7
#pragma unroll
    for (int i = 0; i < 4; i++)
        t[ty + 8 * i][tx] = wmma::__float_to_tf32(W[(size_t)(k0 + ty + 8 * i) * D_ + n0 + tx]);
    __syncthreads();
#pragma unroll
    for (int i = 0; i < 4; i++)
        g_wt[(size_t)(z * D_ + n0 + ty + 8 * i) * D_ + k0 + tx] = t[tx][ty + 8 * i];
}

__global__ __launch_bounds__(256) void prep_bias(
    const float* __restrict__ bq, const float* __restrict__ bk,
    const float* __restrict__ bv, const float* __restrict__ bo)
{
    int idx = blockIdx.x * 256 + threadIdx.x;   // 3072
    int z = idx / D_, j = idx - z * D_;
    const float* s = (z == 0) ? bq : (z == 1) ? bk : (z == 2) ? bv : bo;
    g_bias[idx] = s[j];
}

// ---------------------------------------------------------------------------
// GEMM: CTA tile 128(M) x 256(N), warp tile 64x64 (2x4 warps), K-chunk 16,
// double-buffered cp.async.  B operand = g_wt [n][k] -> wmma col_major.
// MODE 0: A=g_x, out g_q/g_k/g_v (+bias, round).  grid (256, 9)
// MODE 1: A=g_o, out g_y (+bias +residual).       grid (256, 3)
// ---------------------------------------------------------------------------
#define AST 20
#define A_BUF (128 * AST)           /* floats */
#define B_BUF (256 * AST)
#define STAGEF (A_BUF + B_BUF)      /* 7680 floats = 30720 B */
#define GEMM_SMEM (128 * 132 * 4)   /* 67584 B; pipeline (61440) fits inside */

typedef wmma::fragment<wmma::matrix_a, 16, 16, 8, wmma::precision::tf32, wmma::row_major> FragA;
typedef wmma::fragment<wmma::matrix_b, 16, 16, 8, wmma::precision::tf32, wmma::row_major> FragB;
typedef wmma::fragment<wmma::matrix_b, 16, 16, 8, wmma::precision::tf32, wmma::col_major> FragBc;
typedef wmma::fragment<wmma::accumulator, 16, 16, 8, float> FragC;

__device__ __forceinline__ void ld_stage(const float* Ap, const float* Bp,
                                         uint32_t smb, int tid, int m0, int wrow0, int jt)
{
    const uint32_t sb = smb + (jt & 1) * (STAGEF * 4);
    const int k0 = jt * 16;
#pragma unroll
    for (int i = 0; i < 2; i++) {                 // A: 512 float4
        int idx = tid + i * 256;
        int r = idx >> 2, c = (idx & 3) << 2;
        cpa16(sb + (r * AST + c) * 4, Ap + (size_t)(m0 + r) * D_ + k0 + c);
    }
#pragma unroll
    for (int i = 0; i < 4; i++) {                 // B: 1024 float4
        int idx = tid + i * 256;
        int r = idx >> 2, c = (idx & 3) << 2;
        cpa16(sb + (A_BUF + r * AST + c) * 4, Bp + (size_t)(wrow0 + r) * D_ + k0 + c);
    }
    cp_commit();
}

template <int MODE>
__global__ __launch_bounds__(256, 1) void gemm_kernel(const float* __restrict__ X)
{
    const uint32_t smb = smem_u32(dynsm);
    const int m0 = blockIdx.x * 128;
    const int ytile = blockIdx.y;
    const int wrow0 = (MODE == 0) ? ytile * 256 : 2304 + ytile * 256;
    const float* Ap = (MODE == 0) ? g_x : g_o;

    const int tid = threadIdx.x;
    const int wid = tid >> 5;
    const int wm = wid >> 2;     // 0..1
    const int wn = wid & 3;      // 0..3

    FragC acc[4][4];
#pragma unroll
    for (int i = 0; i < 4; i++)
#pragma unroll
        for (int j = 0; j < 4; j++) wmma::fill_fragment(acc[i][j], 0.0f);

    ld_stage(Ap, g_wt, smb, tid, m0, wrow0, 0);

    for (int it = 0; it < 48; it++) {
        if (it < 47) {
            ld_stage(Ap, g_wt, smb, tid, m0, wrow0, it + 1);
            cp_wait<1>();
        } else {
            cp_wait<0>();
        }
        __syncthreads();

        const float* Ab = dynsm + (it & 1) * STAGEF;
        const float* Bb = Ab + A_BUF;
#pragma unroll
        for (int ks = 0; ks < 2; ks++) {
            FragA a[4];
            FragBc b[4];
#pragma unroll
            for (int i = 0; i < 4; i++)
                wmma::load_matrix_sync(a[i], Ab + (wm * 64 + i * 16) * AST + ks * 8, AST);
#pragma unroll
            for (int j = 0; j < 4; j++)
                wmma::load_matrix_sync(b[j], Bb + (wn * 64 + j * 16) * AST + ks * 8, AST);
#pragma unroll
            for (int i = 0; i < 4; i++)
#pragma unroll
                for (int j = 0; j < 4; j++)
                    wmma::mma_sync(acc[i][j], a[i], b[j], acc[i][j]);
        }
        __syncthreads();
    }

    // Epilogue: two N=128 halves via smem staging [128][132]
    float* St = dynsm;
#pragma unroll
    for (int half = 0; half < 2; half++) {
        if ((wn >> 1) == half) {
            const int cb = (wn & 1) * 64;
#pragma unroll
            for (int i = 0; i < 4; i++)
#pragma unroll
                for (int j = 0; j < 4; j++)
                    wmma::store_matrix_sync(St + (wm * 64 + i * 16) * 132 + cb + j * 16,
                                            acc[i][j], 132, wmma::mem_row_major);
        }
        __syncthreads();

        const int ycol = (MODE == 0 ? ytile * 256 : ytile * 256) + half * 128;
        if (MODE == 0) {
            const int z = ycol / D_;
            const int n0 = ycol - z * D_;
            const float* bb = g_bias + ycol;
            float* Out = (z == 0) ? g_q : (z == 1) ? g_k : g_v;
#pragma unroll
            for (int i = 0; i < 16; i++) {
                int idx = tid + i * 256;
                int r = idx >> 5, c4 = (idx & 31) << 2;
                float4 v = *(const float4*)(St + r * 132 + c4);
                const float4 bv = *(const float4*)(bb + c4);
                v.x = wmma::__float_to_tf32(v.x + bv.x);
                v.y = wmma::__float_to_tf32(v.y + bv.y);
                v.z = wmma::__float_to_tf32(v.z + bv.z);
                v.w = wmma::__float_to_tf32(v.w + bv.w);
                *(float4*)(Out + (size_t)(m0 + r) * D_ + n0 + c4) = v;
            }
        } else {
            const int n0 = ycol;
            const float* bb = g_bias + 2304 + n0;
#pragma unroll
            for (int i = 0; i < 16; i++) {
                int idx = tid + i * 256;
                int r = idx >> 5, c4 = (idx & 31) << 2;
                float4 v = *(const float4*)(St + r * 132 + c4);
                const float4 bv = *(const float4*)(bb + c4);
                int tok = m0 + r;
                int b = tok >> 13;
                int l = tok & (LP_ - 1);
                float4 res = make_float4(0.f, 0.f, 0.f, 0.f);
                if (l < L_) res = *(const float4*)(X + (size_t)(b * L_ + l) * D_ + n0 + c4);
                v.x += bv.x + res.x;
                v.y += bv.y + res.y;
                v.z += bv.z + res.z;
                v.w += bv.w + res.w;
                *(float4*)(g_y + (size_t)tok * D_ + n0 + c4) = v;
            }
        }
        __syncthreads();
    }
}

// ---------------------------------------------------------------------------
// Attention per (head, window). S overlays Q+K smem (dead after QK^T).
// ---------------------------------------------------------------------------
#define QKV_STRIDE 68
#define S_STRIDE   132
#define ATTN_SMEM (3 * 128 * QKV_STRIDE * 4)   /* 104448 B */

__global__ __launch_bounds__(256) void attn_kernel()
{
    float* sm = dynsm;
    float* Q = sm;
    float* K = Q + 128 * QKV_STRIDE;
    float* V = K + 128 * QKV_STRIDE;
    float* S = sm;                        // overlays Q+K after QK^T

    const int h = blockIdx.x;
    const int tok0 = blockIdx.y * 128;
    const int tid = threadIdx.x;
    const int wid = tid >> 5;
    const int wm = wid >> 1;
    const int wn = wid & 1;

#pragma unroll
    for (int it = 0; it < 8; it++) {
        int idx = tid + it * 256;
        int r = idx >> 4;
        int c4 = (idx & 15) * 4;
        size_t g = (size_t)(tok0 + r) * D_ + h * HD_ + c4;
        *(float4*)(Q + r * QKV_STRIDE + c4) = *(const float4*)(g_q + g);
        *(float4*)(K + r * QKV_STRIDE + c4) = *(const float4*)(g_k + g);
        *(float4*)(V + r * QKV_STRIDE + c4) = *(const float4*)(g_v + g);
    }
    __syncthreads();

    {
        FragC acc[2][4];
#pragma unroll
        for (int i = 0; i < 2; i++)
#pragma unroll
            for (int j = 0; j < 4; j++) wmma::fill_fragment(acc[i][j], 0.0f);
#pragma unroll
        for (int kk = 0; kk < 8; kk++) {
            FragA a0, a1;
            wmma::load_matrix_sync(a0, Q + (wm * 32) * QKV_STRIDE + kk * 8, QKV_STRIDE);
            wmma::load_matrix_sync(a1, Q + (wm * 32 + 16) * QKV_STRIDE + kk * 8, QKV_STRIDE);
#pragma unroll
            for (int j = 0; j < 4; j++) {
                FragBc bf;
                wmma::load_matrix_sync(bf, K + (wn * 64 + j * 16) * QKV_STRIDE + kk * 8, QKV_STRIDE);
                wmma::mma_sync(acc[0][j], a0, bf, acc[0][j]);
                wmma::mma_sync(acc[1][j], a1, bf, acc[1][j]);
            }
        }
        __syncthreads();   // all warps done reading Q/K before S overlays them
#pragma unroll
        for (int i = 0; i < 2; i++)
#pragma unroll
            for (int j = 0; j < 4; j++)
                wmma::store_matrix_sync(S + (wm * 32 + i * 16) * S_STRIDE + wn * 64 + j * 16,
                                        acc[i][j], S_STRIDE, wmma::mem_row_major);
    }
    __syncthreads();

    if (tid < 128) {
        float4* row = (float4*)(S + tid * S_STRIDE);
        const float scale = 0.125f;
        float mx = -3.4e38f;
#pragma unroll
        for (int j = 0; j < 32; j++) {
            float4 v = row[j];
            mx = fmaxf(mx, fmaxf(fmaxf(v.x, v.y), fmaxf(v.z, v.w)));
        }
        mx *= scale;
        float sum = 0.0f;
#pragma unroll
        for (int j = 0; j < 32; j++) {
            float4 v = row[j];
            v.x = __expf(v.x * scale - mx);
            v.y = __expf(v.y * scale - mx);
            v.z = __expf(v.z * scale - mx);
            v.w = __expf(v.w * scale - mx);
            sum += v.x + v.y + v.z + v.w;
            row[j] = v;
        }
        float inv = 1.0f / sum;
#pragma unroll
        for (int j = 0; j < 32; j++) {
            float4 v = row[j];
            v.x = wmma::__float_to_tf32(v.x * inv);
            v.y = wmma::__float_to_tf32(v.y * inv);
            v.z = wmma::__float_to_tf32(v.z * inv);
            v.w = wmma::__float_to_tf32(v.w * inv);
            row[j] = v;
        }
    }
    __syncthreads();

    {
        FragC acc[2][2];
#pragma unroll
        for (int i = 0; i < 2; i++)
#pragma unroll
            for (int j = 0; j < 2; j++) wmma::fill_fragment(acc[i][j], 0.0f);
#pragma unroll
        for (int kk = 0; kk < 16; kk++) {
            FragA a0, a1;
            FragB bf0, bf1;
            wmma::load_matrix_sync(a0, S + (wm * 32) * S_STRIDE + kk * 8, S_STRIDE);
            wmma::load_matrix_sync(a1, S + (wm * 32 + 16) * S_STRIDE + kk * 8, S_STRIDE);
            wmma::load_matrix_sync(bf0, V + (kk * 8) * QKV_STRIDE + wn * 32, QKV_STRIDE);
            wmma::load_matrix_sync(bf1, V + (kk * 8) * QKV_STRIDE + wn * 32 + 16, QKV_STRIDE);
            wmma::mma_sync(acc[0][0], a0, bf0, acc[0][0]);
            wmma::mma_sync(acc[0][1], a0, bf1, acc[0][1]);
            wmma::mma_sync(acc[1][0], a1, bf0, acc[1][0]);
            wmma::mma_sync(acc[1][1], a1, bf1, acc[1][1]);
        }
#pragma unroll
        for (int i = 0; i < 2; i++)
#pragma unroll
            for (int j = 0; j < 2; j++) {
#pragma unroll
                for (int e = 0; e < acc[i][j].num_elements; e++)
                    acc[i][j].x[e] = wmma::__float_to_tf32(acc[i][j].x[e]);
                wmma::store_matrix_sync(
                    g_o + (size_t)(tok0 + wm * 32 + i * 16) * D_ + h * HD_ + wn * 32 + j * 16,
                    acc[i][j], D_, wmma::mem_row_major);
            }
    }
}

// ---------------------------------------------------------------------------
// LayerNorm
// ---------------------------------------------------------------------------
__global__ __launch_bounds__(256) void ln_kernel(
    const float* __restrict__ gam, const float* __restrict__ bet,
    float* __restrict__ out)
{
    const int t = blockIdx.x;
    const int b = t / L_;
    const int l = t - b * L_;
    const float* y = g_y + (size_t)(b * LP_ + l) * D_;
    const int tid = threadIdx.x;

    float v0 = y[tid], v1 = y[tid + 256], v2 = y[tid + 512];
    float s = v0 + v1 + v2;
    float ss = v0 * v0 + v1 * v1 + v2 * v2;

    __shared__ float red_s[8], red_q[8];
#pragma unroll
    for (int off = 16; off > 0; off >>= 1) {
        s += __shfl_down_sync(0xffffffffu, s, off);
        ss += __shfl_down_sync(0xffffffffu, ss, off);
    }
    if ((tid & 31) == 0) { red_s[tid >> 5] = s; red_q[tid >> 5] = ss; }
    __syncthreads();
    if (tid < 32) {
        float a = (tid < 8) ? red_s[tid] : 0.0f;
        float q = (tid < 8) ? red_q[tid] : 0.0f;
#pragma unroll
        for (int off = 4; off > 0; off >>= 1) {
            a += __shfl_down_sync(0xffffffffu, a, off);
            q += __shfl_down_sync(0xffffffffu, q, off);
        }
        if (tid == 0) { red_s[0] = a; red_q[0] = q; }
    }
    __syncthreads();

    float mu = red_s[0] * (1.0f / D_);
    float var = red_q[0] * (1.0f / D_) - mu * mu;
    float inv = rsqrtf(var + 1e-5f);

    float* o = out + (size_t)t * D_;
    o[tid]       = (v0 - mu) * inv * gam[tid]       + bet[tid];
    o[tid + 256] = (v1 - mu) * inv * gam[tid + 256] + bet[tid + 256];
    o[tid + 512] = (v2 - mu) * inv * gam[tid + 512] + bet[tid + 512];
}

// ---------------------------------------------------------------------------
extern "C" void kernel_launch(void* const* d_in, const int* in_sizes, int n_in,
                              void* d_out, int out_size)
{
    const float* x    = (const float*)d_in[0];
    const float* Wq   = (const float*)d_in[1];
    const float* bq   = (const float*)d_in[2];
    const float* Wk   = (const float*)d_in[3];
    const float* bk   = (const float*)d_in[4];
    const float* Wv   = (const float*)d_in[5];
    const float* bv   = (const float*)d_in[6];
    const float* Wo   = (const float*)d_in[7];
    const float* bo   = (const float*)d_in[8];
    const float* ln_g = (const float*)d_in[9];
    const float* ln_b = (const float*)d_in[10];
    float* out = (float*)d_out;

    cudaFuncSetAttribute(gemm_kernel<0>, cudaFuncAttributeMaxDynamicSharedMemorySize, GEMM_SMEM);
    cudaFuncSetAttribute(gemm_kernel<1>, cudaFuncAttributeMaxDynamicSharedMemorySize, GEMM_SMEM);
    cudaFuncSetAttribute(attn_kernel, cudaFuncAttributeMaxDynamicSharedMemorySize, ATTN_SMEM);

    prep_x<<<24576, 256>>>(x);
    prep_wt<<<dim3(24, 24, 4), 256>>>(Wq, Wk, Wv, Wo);
    prep_bias<<<12, 256>>>(bq, bk, bv, bo);
    gemm_kernel<0><<<dim3(NTOK / 128, 9), 256, GEMM_SMEM>>>(nullptr);
    attn_kernel<<<dim3(H_, NTOK / WSZ), 256, ATTN_SMEM>>>();
    gemm_kernel<1><<<dim3(NTOK / 128, 3), 256, GEMM_SMEM>>>(x);
    ln_kernel<<<B_ * L_, 256>>>(ln_g, ln_b, out);
}

// round 5
// speedup vs baseline: 1.3298x; 1.0010x over previous
#include <cuda_runtime.h>
#include <mma.h>
#include <math.h>
#include <stdint.h>

using namespace nvcuda;

#define D_   768
#define H_   12
#define HD_  64
#define WSZ  128
#define B_   4
#define L_   8190
#define LP_  8192
#define NTOK (B_*LP_)   /* 32768 */

// Scratch
__device__ float g_x[(size_t)NTOK * D_];     // rounded + zero-padded input
__device__ float g_wt[4 * 589824];           // rounded, TRANSPOSED weights: [z*768+n][k]
__device__ float g_bias[4 * D_];             // concat bq,bk,bv,bo
__device__ float g_q[(size_t)NTOK * D_];
__device__ float g_k[(size_t)NTOK * D_];
__device__ float g_v[(size_t)NTOK * D_];
__device__ float g_o[(size_t)NTOK * D_];
__device__ float g_y[(size_t)NTOK * D_];

__device__ __forceinline__ void cpa16(uint32_t s, const float* g) {
    asm volatile("cp.async.cg.shared.global [%0], [%1], 16;" :: "r"(s), "l"(g));
}
template<int N> __device__ __forceinline__ void cp_wait() {
    asm volatile("cp.async.wait_group %0;" :: "n"(N));
}
__device__ __forceinline__ void cp_commit() {
    asm volatile("cp.async.commit_group;");
}
__device__ __forceinline__ uint32_t smem_u32(const void* p) {
    uint32_t a;
    asm("{ .reg .u64 t; cvta.to.shared.u64 t, %1; cvt.u32.u64 %0, t; }" : "=r"(a) : "l"(p));
    return a;
}

extern __shared__ __align__(1024) float dynsm[];

// ---------------------------------------------------------------------------
// Prep kernels
// ---------------------------------------------------------------------------
__global__ __launch_bounds__(256) void prep_x(const float* __restrict__ X)
{
    size_t fidx = (size_t)blockIdx.x * 256 + threadIdx.x;   // 6291456 float4s
    int tok = (int)(fidx / 192);
    int c4  = (int)(fidx - (size_t)tok * 192) * 4;
    int b = tok >> 13;
    int l = tok & (LP_ - 1);
    float4 v = make_float4(0.f, 0.f, 0.f, 0.f);
    if (l < L_) v = *(const float4*)(X + (size_t)(b * L_ + l) * D_ + c4);
    v.x = wmma::__float_to_tf32(v.x);
    v.y = wmma::__float_to_tf32(v.y);
    v.z = wmma::__float_to_tf32(v.z);
    v.w = wmma::__float_to_tf32(v.w);
    *(float4*)(g_x + fidx * 4) = v;
}

// transpose + round weights: g_wt[(z*768 + n)*768 + k] = rnd(W_z[k][n])
__global__ __launch_bounds__(256) void prep_wt(
    const float* __restrict__ Wq, const float* __restrict__ Wk,
    const float* __restrict__ Wv, const float* __restrict__ Wo)
{
    __shared__ float t[32][33];
    const int z = blockIdx.z;
    const float* W = (z == 0) ? Wq : (z == 1) ? Wk : (z == 2) ? Wv : Wo;
    const int k0 = blockIdx.x * 32;
    const int n0 = blockIdx.y * 32;
    const int tx = threadIdx.x & 31;
    const int ty = threadIdx.x >> 5;      // 0..7
#pragma unroll
    for (int i = 0; i < 4; i++)
        t[ty + 8 * i][tx] = wmma::__float_to_tf32(W[(size_t)(k0 + ty + 8 * i) * D_ + n0 + tx]);
    __syncthreads();
#pragma unroll
    for (int i = 0; i < 4; i++)
        g_wt[(size_t)(z * D_ + n0 + ty + 8 * i) * D_ + k0 + tx] = t[tx][ty + 8 * i];
}

__global__ __launch_bounds__(256) void prep_bias(
    const float* __restrict__ bq, const float* __restrict__ bk,
    const float* __restrict__ bv, const float* __restrict__ bo)
{
    int idx = blockIdx.x * 256 + threadIdx.x;   // 3072
    int z = idx / D_, j = idx - z * D_;
    const float* s = (z == 0) ? bq : (z == 1) ? bk : (z == 2) ? bv : bo;
    g_bias[idx] = s[j];
}

// ---------------------------------------------------------------------------
// GEMM: CTA tile 128(M) x 256(N), warp tile 64x64 (2x4 warps), K-chunk 16,
// double-buffered cp.async.  B operand = g_wt [n][k] -> wmma col_major.
// MODE 0: A=g_x, out g_q/g_k/g_v (+bias, round).  grid (256, 9)
// MODE 1: A=g_o, out g_y (+bias +residual).       grid (256, 3)
// ---------------------------------------------------------------------------
#define AST 20
#define A_BUF (128 * AST)           /* floats */
#define B_BUF (256 * AST)
#define STAGEF (A_BUF + B_BUF)      /* 7680 floats = 30720 B */
#define GEMM_SMEM (128 * 132 * 4)   /* 67584 B; pipeline (61440) fits inside */

typedef wmma::fragment<wmma::matrix_a, 16, 16, 8, wmma::precision::tf32, wmma::row_major> FragA;
typedef wmma::fragment<wmma::matrix_b, 16, 16, 8, wmma::precision::tf32, wmma::row_major> FragB;
typedef wmma::fragment<wmma::matrix_b, 16, 16, 8, wmma::precision::tf32, wmma::col_major> FragBc;
typedef wmma::fragment<wmma::accumulator, 16, 16, 8, float> FragC;

__device__ __forceinline__ void ld_stage(const float* Ap, const float* Bp,
                                         uint32_t smb, int tid, int m0, int wrow0, int jt)
{
    const uint32_t sb = smb + (jt & 1) * (STAGEF * 4);
    const int k0 = jt * 16;
#pragma unroll
    for (int i = 0; i < 2; i++) {                 // A: 512 float4
        int idx = tid + i * 256;
        int r = idx >> 2, c = (idx & 3) << 2;
        cpa16(sb + (r * AST + c) * 4, Ap + (size_t)(m0 + r) * D_ + k0 + c);
    }
#pragma unroll
    for (int i = 0; i < 4; i++) {                 // B: 1024 float4
        int idx = tid + i * 256;
        int r = idx >> 2, c = (idx & 3) << 2;
        cpa16(sb + (A_BUF + r * AST + c) * 4, Bp + (size_t)(wrow0 + r) * D_ + k0 + c);
    }
    cp_commit();
}

template <int MODE>
__global__ __launch_bounds__(256, 1) void gemm_kernel(const float* __restrict__ X)
{
    const uint32_t smb = smem_u32(dynsm);
    const int m0 = blockIdx.x * 128;
    const int ytile = blockIdx.y;
    const int wrow0 = (MODE == 0) ? ytile * 256 : 2304 + ytile * 256;
    const float* Ap = (MODE == 0) ? g_x : g_o;

    const int tid = threadIdx.x;
    const int wid = tid >> 5;
    const int wm = wid >> 2;     // 0..1
    const int wn = wid & 3;      // 0..3

    FragC acc[4][4];
#pragma unroll
    for (int i = 0; i < 4; i++)
#pragma unroll
        for (int j = 0; j < 4; j++) wmma::fill_fragment(acc[i][j], 0.0f);

    ld_stage(Ap, g_wt, smb, tid, m0, wrow0, 0);

    for (int it = 0; it < 48; it++) {
        if (it < 47) {
            ld_stage(Ap, g_wt, smb, tid, m0, wrow0, it + 1);
            cp_wait<1>();
        } else {
            cp_wait<0>();
        }
        __syncthreads();

        const float* Ab = dynsm + (it & 1) * STAGEF;
        const float* Bb = Ab + A_BUF;
#pragma unroll
        for (int ks = 0; ks < 2; ks++) {
            FragA a[4];
            FragBc b[4];
#pragma unroll
            for (int i = 0; i < 4; i++)
                wmma::load_matrix_sync(a[i], Ab + (wm * 64 + i * 16) * AST + ks * 8, AST);
#pragma unroll
            for (int j = 0; j < 4; j++)
                wmma::load_matrix_sync(b[j], Bb + (wn * 64 + j * 16) * AST + ks * 8, AST);
#pragma unroll
            for (int i = 0; i < 4; i++)
#pragma unroll
                for (int j = 0; j < 4; j++)
                    wmma::mma_sync(acc[i][j], a[i], b[j], acc[i][j]);
        }
        __syncthreads();
    }

    // Epilogue: two N=128 halves via smem staging [128][132]
    float* St = dynsm;
#pragma unroll
    for (int half = 0; half < 2; half++) {
        if ((wn >> 1) == half) {
            const int cb = (wn & 1) * 64;
#pragma unroll
            for (int i = 0; i < 4; i++)
#pragma unroll
                for (int j = 0; j < 4; j++)
                    wmma::store_matrix_sync(St + (wm * 64 + i * 16) * 132 + cb + j * 16,
                                            acc[i][j], 132, wmma::mem_row_major);
        }
        __syncthreads();

        const int ycol = (MODE == 0 ? ytile * 256 : ytile * 256) + half * 128;
        if (MODE == 0) {
            const int z = ycol / D_;
            const int n0 = ycol - z * D_;
            const float* bb = g_bias + ycol;
            float* Out = (z == 0) ? g_q : (z == 1) ? g_k : g_v;
#pragma unroll
            for (int i = 0; i < 16; i++) {
                int idx = tid + i * 256;
                int r = idx >> 5, c4 = (idx & 31) << 2;
                float4 v = *(const float4*)(St + r * 132 + c4);
                const float4 bv = *(const float4*)(bb + c4);
                v.x = wmma::__float_to_tf32(v.x + bv.x);
                v.y = wmma::__float_to_tf32(v.y + bv.y);
                v.z = wmma::__float_to_tf32(v.z + bv.z);
                v.w = wmma::__float_to_tf32(v.w + bv.w);
                *(float4*)(Out + (size_t)(m0 + r) * D_ + n0 + c4) = v;
            }
        } else {
            const int n0 = ycol;
            const float* bb = g_bias + 2304 + n0;
#pragma unroll
            for (int i = 0; i < 16; i++) {
                int idx = tid + i * 256;
                int r = idx >> 5, c4 = (idx & 31) << 2;
                float4 v = *(const float4*)(St + r * 132 + c4);
                const float4 bv = *(const float4*)(bb + c4);
                int tok = m0 + r;
                int b = tok >> 13;
                int l = tok & (LP_ - 1);
                float4 res = make_float4(0.f, 0.f, 0.f, 0.f);
                if (l < L_) res = *(const float4*)(X + (size_t)(b * L_ + l) * D_ + n0 + c4);
                v.x += bv.x + res.x;
                v.y += bv.y + res.y;
                v.z += bv.z + res.z;
                v.w += bv.w + res.w;
                *(float4*)(g_y + (size_t)tok * D_ + n0 + c4) = v;
            }
        }
        __syncthreads();
    }
}

// ---------------------------------------------------------------------------
// Attention per (head, window). S overlays Q+K smem (dead after QK^T).
// ---------------------------------------------------------------------------
#define QKV_STRIDE 68
#define S_STRIDE   132
#define ATTN_SMEM (3 * 128 * QKV_STRIDE * 4)   /* 104448 B */

__global__ __launch_bounds__(256) void attn_kernel()
{
    float* sm = dynsm;
    float* Q = sm;
    float* K = Q + 128 * QKV_STRIDE;
    float* V = K + 128 * QKV_STRIDE;
    float* S = sm;                        // overlays Q+K after QK^T

    const int h = blockIdx.x;
    const int tok0 = blockIdx.y * 128;
    const int tid = threadIdx.x;
    const int wid = tid >> 5;
    const int wm = wid >> 1;
    const int wn = wid & 1;

#pragma unroll
    for (int it = 0; it < 8; it++) {
        int idx = tid + it * 256;
        int r = idx >> 4;
        int c4 = (idx & 15) * 4;
        size_t g = (size_t)(tok0 + r) * D_ + h * HD_ + c4;
        *(float4*)(Q + r * QKV_STRIDE + c4) = *(const float4*)(g_q + g);
        *(float4*)(K + r * QKV_STRIDE + c4) = *(const float4*)(g_k + g);
        *(float4*)(V + r * QKV_STRIDE + c4) = *(const float4*)(g_v + g);
    }
    __syncthreads();

    {
        FragC acc[2][4];
#pragma unroll
        for (int i = 0; i < 2; i++)
#pragma unroll
            for (int j = 0; j < 4; j++) wmma::fill_fragment(acc[i][j], 0.0f);
#pragma unroll
        for (int kk = 0; kk < 8; kk++) {
            FragA a0, a1;
            wmma::load_matrix_sync(a0, Q + (wm * 32) * QKV_STRIDE + kk * 8, QKV_STRIDE);
            wmma::load_matrix_sync(a1, Q + (wm * 32 + 16) * QKV_STRIDE + kk * 8, QKV_STRIDE);
#pragma unroll
            for (int j = 0; j < 4; j++) {
                FragBc bf;
                wmma::load_matrix_sync(bf, K + (wn * 64 + j * 16) * QKV_STRIDE + kk * 8, QKV_STRIDE);
                wmma::mma_sync(acc[0][j], a0, bf, acc[0][j]);
                wmma::mma_sync(acc[1][j], a1, bf, acc[1][j]);
            }
        }
        __syncthreads();   // all warps done reading Q/K before S overlays them
#pragma unroll
        for (int i = 0; i < 2; i++)
#pragma unroll
            for (int j = 0; j < 4; j++)
                wmma::store_matrix_sync(S + (wm * 32 + i * 16) * S_STRIDE + wn * 64 + j * 16,
                                        acc[i][j], S_STRIDE, wmma::mem_row_major);
    }
    __syncthreads();

    if (tid < 128) {
        float4* row = (float4*)(S + tid * S_STRIDE);
        const float scale = 0.125f;
        float mx = -3.4e38f;
#pragma unroll
        for (int j = 0; j < 32; j++) {
            float4 v = row[j];
            mx = fmaxf(mx, fmaxf(fmaxf(v.x, v.y), fmaxf(v.z, v.w)));
        }
        mx *= scale;
        float sum = 0.0f;
#pragma unroll
        for (int j = 0; j < 32; j++) {
            float4 v = row[j];
            v.x = __expf(v.x * scale - mx);
            v.y = __expf(v.y * scale - mx);
            v.z = __expf(v.z * scale - mx);
            v.w = __expf(v.w * scale - mx);
            sum += v.x + v.y + v.z + v.w;
            row[j] = v;
        }
        float inv = 1.0f / sum;
#pragma unroll
        for (int j = 0; j < 32; j++) {
            float4 v = row[j];
            v.x = wmma::__float_to_tf32(v.x * inv);
            v.y = wmma::__float_to_tf32(v.y * inv);
            v.z = wmma::__float_to_tf32(v.z * inv);
            v.w = wmma::__float_to_tf32(v.w * inv);
            row[j] = v;
        }
    }
    __syncthreads();

    {
        FragC acc[2][2];
#pragma unroll
        for (int i = 0; i < 2; i++)
#pragma unroll
            for (int j = 0; j < 2; j++) wmma::fill_fragment(acc[i][j], 0.0f);
#pragma unroll
        for (int kk = 0; kk < 16; kk++) {
            FragA a0, a1;
            FragB bf0, bf1;
            wmma::load_matrix_sync(a0, S + (wm * 32) * S_STRIDE + kk * 8, S_STRIDE);
            wmma::load_matrix_sync(a1, S + (wm * 32 + 16) * S_STRIDE + kk * 8, S_STRIDE);
            wmma::load_matrix_sync(bf0, V + (kk * 8) * QKV_STRIDE + wn * 32, QKV_STRIDE);
            wmma::load_matrix_sync(bf1, V + (kk * 8) * QKV_STRIDE + wn * 32 + 16, QKV_STRIDE);
            wmma::mma_sync(acc[0][0], a0, bf0, acc[0][0]);
            wmma::mma_sync(acc[0][1], a0, bf1, acc[0][1]);
            wmma::mma_sync(acc[1][0], a1, bf0, acc[1][0]);
            wmma::mma_sync(acc[1][1], a1, bf1, acc[1][1]);
        }
#pragma unroll
        for (int i = 0; i < 2; i++)
#pragma unroll
            for (int j = 0; j < 2; j++) {
#pragma unroll
                for (int e = 0; e < acc[i][j].num_elements; e++)
                    acc[i][j].x[e] = wmma::__float_to_tf32(acc[i][j].x[e]);
                wmma::store_matrix_sync(
                    g_o + (size_t)(tok0 + wm * 32 + i * 16) * D_ + h * HD_ + wn * 32 + j * 16,
                    acc[i][j], D_, wmma::mem_row_major);
            }
    }
}

// ---------------------------------------------------------------------------
// LayerNorm
// ---------------------------------------------------------------------------
__global__ __launch_bounds__(256) void ln_kernel(
    const float* __restrict__ gam, const float* __restrict__ bet,
    float* __restrict__ out)
{
    const int t = blockIdx.x;
    const int b = t / L_;
    const int l = t - b * L_;
    const float* y = g_y + (size_t)(b * LP_ + l) * D_;
    const int tid = threadIdx.x;

    float v0 = y[tid], v1 = y[tid + 256], v2 = y[tid + 512];
    float s = v0 + v1 + v2;
    float ss = v0 * v0 + v1 * v1 + v2 * v2;

    __shared__ float red_s[8], red_q[8];
#pragma unroll
    for (int off = 16; off > 0; off >>= 1) {
        s += __shfl_down_sync(0xffffffffu, s, off);
        ss += __shfl_down_sync(0xffffffffu, ss, off);
    }
    if ((tid & 31) == 0) { red_s[tid >> 5] = s; red_q[tid >> 5] = ss; }
    __syncthreads();
    if (tid < 32) {
        float a = (tid < 8) ? red_s[tid] : 0.0f;
        float q = (tid < 8) ? red_q[tid] : 0.0f;
#pragma unroll
        for (int off = 4; off > 0; off >>= 1) {
            a += __shfl_down_sync(0xffffffffu, a, off);
            q += __shfl_down_sync(0xffffffffu, q, off);
        }
        if (tid == 0) { red_s[0] = a; red_q[0] = q; }
    }
    __syncthreads();

    float mu = red_s[0] * (1.0f / D_);
    float var = red_q[0] * (1.0f / D_) - mu * mu;
    float inv = rsqrtf(var + 1e-5f);

    float* o = out + (size_t)t * D_;
    o[tid]       = (v0 - mu) * inv * gam[tid]       + bet[tid];
    o[tid + 256] = (v1 - mu) * inv * gam[tid + 256] + bet[tid + 256];
    o[tid + 512] = (v2 - mu) * inv * gam[tid + 512] + bet[tid + 512];
}

// ---------------------------------------------------------------------------
extern "C" void kernel_launch(void* const* d_in, const int* in_sizes, int n_in,
                              void* d_out, int out_size)
{
    const float* x    = (const float*)d_in[0];
    const float* Wq   = (const float*)d_in[1];
    const float* bq   = (const float*)d_in[2];
    const float* Wk   = (const float*)d_in[3];
    const float* bk   = (const float*)d_in[4];
    const float* Wv   = (const float*)d_in[5];
    const float* bv   = (const float*)d_in[6];
    const float* Wo   = (const float*)d_in[7];
    const float* bo   = (const float*)d_in[8];
    const float* ln_g = (const float*)d_in[9];
    const float* ln_b = (const float*)d_in[10];
    float* out = (float*)d_out;

    cudaFuncSetAttribute(gemm_kernel<0>, cudaFuncAttributeMaxDynamicSharedMemorySize, GEMM_SMEM);
    cudaFuncSetAttribute(gemm_kernel<1>, cudaFuncAttributeMaxDynamicSharedMemorySize, GEMM_SMEM);
    cudaFuncSetAttribute(attn_kernel, cudaFuncAttributeMaxDynamicSharedMemorySize, ATTN_SMEM);

    prep_x<<<24576, 256>>>(x);
    prep_wt<<<dim3(24, 24, 4), 256>>>(Wq, Wk, Wv, Wo);
    prep_bias<<<12, 256>>>(bq, bk, bv, bo);
    gemm_kernel<0><<<dim3(NTOK / 128, 9), 256, GEMM_SMEM>>>(nullptr);
    attn_kernel<<<dim3(H_, NTOK / WSZ), 256, ATTN_SMEM>>>();
    gemm_kernel<1><<<dim3(NTOK / 128, 3), 256, GEMM_SMEM>>>(x);
    ln_kernel<<<B_ * L_, 256>>>(ln_g, ln_b, out);
}